// round 13
// baseline (speedup 1.0000x reference)
#include <cuda_runtime.h>
#include <math.h>
#include <stdint.h>
#include <stddef.h>

#define NB 8
#define LL 2048
#define NL (NB*LL)
#define KROW (LL/2)   // u32 (bf16x2) per K row

// ---------------- device scratch (no allocations allowed) ----------------
static __device__ float4 g_qpack[NL];   // {qx,qy,qz, 0.5*|q|^2 * log2e}
static __device__ float4 g_ppack[NL];   // {px,py,pz, 0.5*|p|^2 * log2e}
static __device__ float  g_u[NL];       // exp(f)
static __device__ float  g_v[NL];       // exp(g)
static __device__ float  g_spart[4*NL]; // cross-block partial sums
static __device__ int    g_ctr[256];    // arrival counters (f-update)
static __device__ int    g_ctr2[256];   // arrival counters (g-update)
static __device__ float  g_cnt[NB];
static __device__ float  g_ab[NB];      // a = b = 1/count
static __device__ float  g_cp[NB][3];
static __device__ float  g_ct[NB][3];
static __device__ float  g_R[NB][9];
// Gibbs kernel K = exp(-M) in bf16 pairs, row-major. 67 MB.
static __device__ unsigned int g_K[(size_t)NB * LL * KROW];

#define L2E  1.4426950408889634f
#define LN2  0.6931471805599453f
#define E005 1.0512710963760241f    // exp(0.05) (diag bias: cost -0.1 => M -0.05)

__device__ __forceinline__ float ex2f_(float x){ float r; asm("ex2.approx.ftz.f32 %0,%1;" : "=f"(r) : "f"(x)); return r; }
__device__ __forceinline__ float lg2f_(float x){ float r; asm("lg2.approx.ftz.f32 %0,%1;" : "=f"(r) : "f"(x)); return r; }
__device__ __forceinline__ float bflo(unsigned int k){ return __uint_as_float(k << 16); }
__device__ __forceinline__ float bfhi(unsigned int k){ return __uint_as_float(k & 0xffff0000u); }

// ---------------- prep ----------------
__global__ void k_zero(){ if (threadIdx.x < NB) g_cnt[threadIdx.x] = 0.f; }

__global__ void k_prep(const float* __restrict__ pred, const float* __restrict__ tru,
                       const float* __restrict__ mgen){
    int t = blockIdx.x*256 + threadIdx.x;   // 0..NL-1
    float px = pred[3*t+0], py = pred[3*t+1], pz = pred[3*t+2];
    float qx = tru [3*t+0], qy = tru [3*t+1], qz = tru [3*t+2];
    g_ppack[t] = make_float4(px,py,pz, 0.5f*(px*px+py*py+pz*pz)*L2E);
    g_qpack[t] = make_float4(qx,qy,qz, 0.5f*(qx*qx+qy*qy+qz*qz)*L2E);
    g_v[t] = 1.0f;                          // v = exp(g), g starts at 0
    __shared__ float sred[256];
    sred[threadIdx.x] = (mgen[t] != 0.f) ? 1.f : 0.f;
    __syncthreads();
    for (int s = 128; s > 0; s >>= 1){
        if (threadIdx.x < s) sred[threadIdx.x] += sred[threadIdx.x+s];
        __syncthreads();
    }
    if (threadIdx.x == 0) atomicAdd(&g_cnt[blockIdx.x>>3], sred[0]);  // 8 blocks per batch
}

__global__ void k_prep2(){
    if (threadIdx.x < NB) g_ab[threadIdx.x] = 1.0f / fmaxf(g_cnt[threadIdx.x], 1.f);
}

// ---------------- build K = exp(-M) once (bf16, row-major) ----------------
// block: 64 rows x 512 cols. warp = row; lane = col pair.
// Limited unroll + launch bounds to keep regs ~40 (R12 had regs=80, occ 33%).
__global__ void __launch_bounds__(256, 6) k_exp(){
    __shared__ float4 tile[512];
    int b = blockIdx.x;
    int qtr = b & 3, rg = b >> 2, n = rg >> 5;
    int row0 = (rg & 31) << 6, c0 = qtr << 9;
    int tid = threadIdx.x, w = tid >> 5, lane = tid & 31;

    for (int i = tid; i < 512; i += 256) tile[i] = g_qpack[n*LL + c0 + i];
    __syncthreads();

    #pragma unroll 1
    for (int i = 0; i < 8; i++){
        int r = row0 + w + 8*i;
        float4 pp = g_ppack[n*LL + r];
        float px = pp.x*L2E, py = pp.y*L2E, pz = pp.z*L2E, pw = pp.w;
        unsigned int* dst = g_K + ((size_t)n*LL + r)*KROW + (c0 >> 1);
        #pragma unroll 2
        for (int j = 0; j < 8; j++){
            int p = lane + 32*j;             // pair index within 512-col strip
            float4 t0 = tile[2*p], t1 = tile[2*p+1];
            // arg = log2e*(p.q - |p|^2/2 - |q|^2/2) = -M*log2e
            float a0 = fmaf(px,t0.x, fmaf(py,t0.y, fmaf(pz,t0.z, -(pw + t0.w))));
            float a1 = fmaf(px,t1.x, fmaf(py,t1.y, fmaf(pz,t1.z, -(pw + t1.w))));
            float e0 = ex2f_(a0), e1 = ex2f_(a1);
            int gc = c0 + 2*p;
            if (gc     == r) e0 *= E005;     // diag bias folded into K
            if (gc + 1 == r) e1 *= E005;
            unsigned int kk;
            asm("cvt.rn.bf16x2.f32 %0, %1, %2;" : "=r"(kk) : "f"(e1), "f"(e0));
            dst[p] = kk;                     // low half = col gc, high = gc+1
        }
    }
}

// ---------------- f half-update: u = a / (K v)  (row-parallel) ----------------
// block: 64 rows x 512 cols; 4 column-quarters combined via g_spart + g_ctr.
// uint4 K loads (16B/lane = 8 cols) for fewer LDGs / more bytes in flight.
__global__ void __launch_bounds__(256, 8) k_mvf(){
    __shared__ float4 vsm[128];              // 512 v values
    __shared__ int lastflag;
    int b = blockIdx.x;
    int qtr = b & 3, rg = b >> 2, n = rg >> 5;
    int row0 = (rg & 31) << 6, c0 = qtr << 9;
    int tid = threadIdx.x, w = tid >> 5, lane = tid & 31;

    float* vf = (float*)vsm;
    for (int i = tid; i < 512; i += 256) vf[i] = g_v[n*LL + c0 + i];
    __syncthreads();

    for (int i = 0; i < 8; i++){
        int r = row0 + w + 8*i;
        const uint4* Kr = (const uint4*)(g_K + ((size_t)n*LL + r)*KROW + (c0 >> 1));
        float acc = 0.f;
        #pragma unroll
        for (int s = 0; s < 2; s++){
            int e = lane + 32*s;             // uint4 = 8 cols; vsm float4 pair 2e,2e+1
            uint4 kk = Kr[e];
            float4 v0 = vsm[2*e], v1 = vsm[2*e+1];
            acc = fmaf(bflo(kk.x), v0.x,
                  fmaf(bfhi(kk.x), v0.y,
                  fmaf(bflo(kk.y), v0.z,
                  fmaf(bfhi(kk.y), v0.w,
                  fmaf(bflo(kk.z), v1.x,
                  fmaf(bfhi(kk.z), v1.y,
                  fmaf(bflo(kk.w), v1.z,
                  fmaf(bfhi(kk.w), v1.w, acc))))))));
        }
        #pragma unroll
        for (int o = 16; o; o >>= 1) acc += __shfl_xor_sync(0xFFFFFFFFu, acc, o);
        if (lane == 0) __stcg(&g_spart[qtr*NL + n*LL + r], acc);
    }
    __threadfence();
    __syncthreads();
    if (tid == 0) lastflag = (atomicAdd(&g_ctr[rg], 1) == 3);
    __syncthreads();
    if (lastflag && w < 2){
        int rr = (w << 5) + lane;
        int gidx = n*LL + row0 + rr;
        float S = __ldcg(&g_spart[gidx])
                + __ldcg(&g_spart[NL   + gidx])
                + __ldcg(&g_spart[2*NL + gidx])
                + __ldcg(&g_spart[3*NL + gidx]);
        g_u[gidx] = __fdividef(g_ab[n], fmaxf(S, 1e-35f));
        if (tid == 0) g_ctr[rg] = 0;
    }
}

// ---------------- g half-update: v = b / (K^T u)  (column-in-register) ------
// block: 512 rows x 64 cols; 4 row-quarters combined via g_spart + g_ctr2.
// K read row-major coalesced (128B per warp-row-step); u broadcast from smem.
__global__ void __launch_bounds__(256, 8) k_mvg(){
    __shared__ float usm[512];
    __shared__ float psum[8][64];
    __shared__ int lastflag;
    int b = blockIdx.x;
    int n = b >> 7, strip = (b >> 2) & 31, rq = b & 3;
    int r0 = rq << 9, c0 = strip << 6;
    int tid = threadIdx.x, cp = tid & 31, rs = tid >> 5;

    for (int i = tid; i < 512; i += 256) usm[i] = g_u[n*LL + r0 + i];
    __syncthreads();

    const unsigned int* Kc = g_K + ((size_t)n*LL + r0)*KROW + (c0 >> 1) + cp;
    float t0 = 0.f, t1 = 0.f;
    #pragma unroll 4
    for (int i = 0; i < 64; i++){
        int lr = rs + 8*i;
        unsigned int kk = Kc[(size_t)lr * KROW];
        float ur = usm[lr];
        t0 = fmaf(bflo(kk), ur, t0);
        t1 = fmaf(bfhi(kk), ur, t1);
    }
    psum[rs][2*cp]   = t0;
    psum[rs][2*cp+1] = t1;
    __syncthreads();
    if (tid < 64){
        float T = 0.f;
        #pragma unroll
        for (int j = 0; j < 8; j++) T += psum[j][tid];
        __stcg(&g_spart[rq*NL + n*LL + c0 + tid], T);
    }
    __threadfence();
    __syncthreads();
    if (tid == 0) lastflag = (atomicAdd(&g_ctr2[n*32 + strip], 1) == 3);
    __syncthreads();
    if (lastflag && tid < 64){
        int gidx = n*LL + c0 + tid;
        float T = __ldcg(&g_spart[gidx])
                + __ldcg(&g_spart[NL   + gidx])
                + __ldcg(&g_spart[2*NL + gidx])
                + __ldcg(&g_spart[3*NL + gidx]);
        g_v[gidx] = __fdividef(g_ab[n], fmaxf(T, 1e-35f));
        if (tid == 0) g_ctr2[n*32 + strip] = 0;
    }
}

// ---------------- pi + true_pos_mapped (full f32 precision) ----------------
// f,g derived inline from u,v: f*L2E = lg2(u), g*L2E = lg2(v).
__global__ void __launch_bounds__(512) k_pi(float* __restrict__ piout, float* __restrict__ tpmout){
    __shared__ float4 tile[LL];
    int n    = blockIdx.x >> 7;          // 128 blocks per batch (16 rows each)
    int row0 = (blockIdx.x & 127) << 4;
    int tid  = threadIdx.x;

    const float4* qp = g_qpack + n*LL;
    const float*  vv = g_v     + n*LL;
    for (int i = tid; i < LL; i += 512){
        float4 c = qp[i];
        c.w = lg2f_(vv[i]) - c.w;        // g*L2E - 0.5|q|^2*L2E
        tile[i] = c;
    }
    __syncthreads();

    int warp = tid >> 5, lane = tid & 31;
    int l = row0 + warp;
    float4 pp = g_ppack[n*LL + l];
    float fp2 = lg2f_(g_u[n*LL + l]) - pp.w;
    float ppx = pp.x*L2E, ppy = pp.y*L2E, ppz = pp.z*L2E;

    float tx=0.f, ty=0.f, tz=0.f;
    float* po = piout + ((size_t)n*LL + l)*LL;
    #pragma unroll 4
    for (int m = lane; m < LL; m += 32){
        float4 c = tile[m];
        float pv = ex2f_(fp2 + fmaf(ppx,c.x, fmaf(ppy,c.y, fmaf(ppz,c.z, c.w))));
        if (m == l) pv *= E005;
        po[m] = pv;
        tx = fmaf(pv, c.x, tx);
        ty = fmaf(pv, c.y, ty);
        tz = fmaf(pv, c.z, tz);
    }
    #pragma unroll
    for (int o = 16; o; o >>= 1){
        tx += __shfl_xor_sync(0xFFFFFFFFu, tx, o);
        ty += __shfl_xor_sync(0xFFFFFFFFu, ty, o);
        tz += __shfl_xor_sync(0xFFFFFFFFu, tz, o);
    }
    if (lane == 0){
        float* tp = tpmout + (size_t)(n*LL + l)*3;
        tp[0] = tx; tp[1] = ty; tp[2] = tz;
    }
}

// ---------------- Kabsch + 3x3 SVD (per batch) ----------------
__global__ void k_kabsch(const float* __restrict__ pred, const float* __restrict__ tpm){
    int n = blockIdx.x, tid = threadIdx.x;
    float s[15];
    #pragma unroll
    for (int k = 0; k < 15; k++) s[k] = 0.f;
    for (int l = tid; l < LL; l += 256){
        const float* p = pred + (size_t)(n*LL + l)*3;
        const float* q = tpm  + (size_t)(n*LL + l)*3;
        float p0=p[0],p1=p[1],p2=p[2], q0=q[0],q1=q[1],q2=q[2];
        s[0]+=p0; s[1]+=p1; s[2]+=p2; s[3]+=q0; s[4]+=q1; s[5]+=q2;
        s[6]+=p0*q0;  s[7]+=p0*q1;  s[8]+=p0*q2;
        s[9]+=p1*q0;  s[10]+=p1*q1; s[11]+=p1*q2;
        s[12]+=p2*q0; s[13]+=p2*q1; s[14]+=p2*q2;
    }
    __shared__ float red[256];
    __shared__ float tot[15];
    for (int k = 0; k < 15; k++){
        red[tid] = s[k]; __syncthreads();
        for (int st = 128; st; st >>= 1){
            if (tid < st) red[tid] += red[tid+st];
            __syncthreads();
        }
        if (tid == 0) tot[k] = red[0];
        __syncthreads();
    }
    if (tid != 0) return;

    double w = fmax((double)g_cnt[n], 1e-6);
    double cp[3] = { tot[0]/w, tot[1]/w, tot[2]/w };
    double cq[3] = { tot[3]/w, tot[4]/w, tot[5]/w };
    double H[3][3];
    for (int i = 0; i < 3; i++)
        for (int j = 0; j < 3; j++)
            H[i][j] = (double)tot[6 + 3*i + j] - w*cp[i]*cq[j];

    double fn = 0.0;
    for (int i = 0; i < 3; i++) for (int j = 0; j < 3; j++) fn += H[i][j]*H[i][j];
    fn = fmax(sqrt(fn), 1e-8);
    double M[3][3];
    for (int i = 0; i < 3; i++)
        for (int j = 0; j < 3; j++)
            M[i][j] = H[i][j]/fn + (i==j ? 1e-4 : 0.0);

    double B[3][3];
    for (int i = 0; i < 3; i++)
        for (int j = 0; j < 3; j++){
            double acc = 0.0;
            for (int k = 0; k < 3; k++) acc += M[k][i]*M[k][j];
            B[i][j] = acc;
        }
    double V[3][3] = {{1,0,0},{0,1,0},{0,0,1}};
    for (int sw = 0; sw < 15; sw++){
        for (int pair = 0; pair < 3; pair++){
            int p = (pair==2) ? 1 : 0;
            int q = (pair==0) ? 1 : 2;
            double apq = B[p][q];
            if (fabs(apq) < 1e-30) continue;
            double tau = (B[q][q] - B[p][p])/(2.0*apq);
            double t = ((tau >= 0.0) ? 1.0 : -1.0)/(fabs(tau) + sqrt(1.0 + tau*tau));
            double c = 1.0/sqrt(1.0 + t*t), sn = t*c;
            for (int k = 0; k < 3; k++){
                double bkp = B[k][p], bkq = B[k][q];
                B[k][p] = c*bkp - sn*bkq; B[k][q] = sn*bkp + c*bkq;
            }
            for (int k = 0; k < 3; k++){
                double bpk = B[p][k], bqk = B[q][k];
                B[p][k] = c*bpk - sn*bqk; B[q][k] = sn*bpk + c*bqk;
            }
            for (int k = 0; k < 3; k++){
                double vkp = V[k][p], vkq = V[k][q];
                V[k][p] = c*vkp - sn*vkq; V[k][q] = sn*vkp + c*vkq;
            }
        }
    }
    double lam[3] = { B[0][0], B[1][1], B[2][2] };
    for (int i = 0; i < 2; i++)
        for (int j = 0; j < 2 - i; j++)
            if (lam[j] < lam[j+1]){
                double tl = lam[j]; lam[j] = lam[j+1]; lam[j+1] = tl;
                for (int k = 0; k < 3; k++){ double tv = V[k][j]; V[k][j] = V[k][j+1]; V[k][j+1] = tv; }
            }
    double detV = V[0][0]*(V[1][1]*V[2][2]-V[1][2]*V[2][1])
                - V[0][1]*(V[1][0]*V[2][2]-V[1][2]*V[2][0])
                + V[0][2]*(V[1][0]*V[2][1]-V[1][1]*V[2][0]);
    if (detV < 0.0) for (int k = 0; k < 3; k++) V[k][2] = -V[k][2];

    double s1 = sqrt(fmax(lam[0], 0.0)), s2 = sqrt(fmax(lam[1], 0.0));
    double u1[3], u2[3], u3[3];
    for (int k = 0; k < 3; k++){
        u1[k] = (M[k][0]*V[0][0] + M[k][1]*V[1][0] + M[k][2]*V[2][0]) / fmax(s1, 1e-30);
        u2[k] = (M[k][0]*V[0][1] + M[k][1]*V[1][1] + M[k][2]*V[2][1]) / fmax(s2, 1e-30);
    }
    double n1 = sqrt(u1[0]*u1[0]+u1[1]*u1[1]+u1[2]*u1[2]);
    for (int k = 0; k < 3; k++) u1[k] /= fmax(n1, 1e-30);
    double d12 = u1[0]*u2[0]+u1[1]*u2[1]+u1[2]*u2[2];
    for (int k = 0; k < 3; k++) u2[k] -= d12*u1[k];
    double n2 = sqrt(u2[0]*u2[0]+u2[1]*u2[1]+u2[2]*u2[2]);
    for (int k = 0; k < 3; k++) u2[k] /= fmax(n2, 1e-30);
    u3[0] = u1[1]*u2[2] - u1[2]*u2[1];
    u3[1] = u1[2]*u2[0] - u1[0]*u2[2];
    u3[2] = u1[0]*u2[1] - u1[1]*u2[0];

    for (int d = 0; d < 3; d++)
        for (int e = 0; e < 3; e++)
            g_R[n][3*d + e] = (float)(u1[d]*V[e][0] + u2[d]*V[e][1] + u3[d]*V[e][2]);
    for (int k = 0; k < 3; k++){ g_cp[n][k] = (float)cp[k]; g_ct[n][k] = (float)cq[k]; }
}

// ---------------- TM score ----------------
__global__ void k_tm(const float* __restrict__ pred, const float* __restrict__ mgen,
                     const float* __restrict__ tpm, float* __restrict__ avg, float inv_d02){
    int n = blockIdx.x, tid = threadIdx.x;
    float R[9];
    #pragma unroll
    for (int k = 0; k < 9; k++) R[k] = g_R[n][k];
    float cp0 = g_cp[n][0], cp1 = g_cp[n][1], cp2 = g_cp[n][2];
    float ct0 = g_ct[n][0], ct1 = g_ct[n][1], ct2 = g_ct[n][2];

    float st = 0.f, sm = 0.f;
    for (int l = tid; l < LL; l += 256){
        const float* p = pred + (size_t)(n*LL + l)*3;
        const float* q = tpm  + (size_t)(n*LL + l)*3;
        float x0 = p[0]-cp0, x1 = p[1]-cp1, x2 = p[2]-cp2;
        float a0 = x0*R[0] + x1*R[3] + x2*R[6] + ct0;
        float a1 = x0*R[1] + x1*R[4] + x2*R[7] + ct1;
        float a2 = x0*R[2] + x1*R[5] + x2*R[8] + ct2;
        float d0 = a0-q[0], d1 = a1-q[1], d2 = a2-q[2];
        float dsq = d0*d0 + d1*d1 + d2*d2;
        float tm = 1.f/(1.f + dsq*inv_d02);
        float mg = mgen[n*LL + l];
        st += tm*mg; sm += mg;
    }
    __shared__ float r1[256], r2[256];
    r1[tid] = st; r2[tid] = sm; __syncthreads();
    for (int s = 128; s; s >>= 1){
        if (tid < s){ r1[tid] += r1[tid+s]; r2[tid] += r2[tid+s]; }
        __syncthreads();
    }
    if (tid == 0) avg[n] = r1[0] / fmaxf(r2[0], 1e-6f);
}

// ---------------- launch ----------------
extern "C" void kernel_launch(void* const* d_in, const int* in_sizes, int n_in,
                              void* d_out, int out_size){
    const float* pred = (const float*)d_in[0];
    const float* tru  = (const float*)d_in[1];
    const float* mgen = (const float*)d_in[2];

    float* out   = (float*)d_out;
    float* avg   = out;                       // (N,)
    float* tpm   = out + NB;                  // (N,L,3)
    float* piout = out + NB + (size_t)NL*3;   // (N,L,L)

    k_zero<<<1, 32>>>();
    k_prep<<<NL/256, 256>>>(pred, tru, mgen);
    k_prep2<<<1, 32>>>();

    k_exp<<<1024, 256>>>();                   // build K once (only exp-heavy pass)

    for (int it = 0; it < 10; it++){
        k_mvf<<<1024, 256>>>();               // u = a / (K v)
        k_mvg<<<1024, 256>>>();               // v = b / (K^T u)
    }

    k_pi<<<1024, 512>>>(piout, tpm);
    k_kabsch<<<NB, 256>>>(pred, tpm);

    double d0 = 1.24 * cbrt((double)((LL > 16 ? LL : 16) - 15)) - 1.8;
    if (d0 < 0.5) d0 = 0.5;
    float inv_d02 = (float)(1.0/(d0*d0));
    k_tm<<<NB, 256>>>(pred, mgen, tpm, avg, inv_d02);
}

// round 14
// speedup vs baseline: 1.1370x; 1.1370x over previous
#include <cuda_runtime.h>
#include <math.h>
#include <stdint.h>
#include <stddef.h>

#define NB 8
#define LL 2048
#define NL (NB*LL)
#define KROW (LL/2)   // u32 (bf16x2) per K row

// ---------------- device scratch (no allocations allowed) ----------------
static __device__ float4 g_qpack[NL];   // {qx,qy,qz, 0.5*|q|^2 * log2e}
static __device__ float4 g_ppack[NL];   // {px,py,pz, 0.5*|p|^2 * log2e}
static __device__ float  g_u[NL];       // exp(f)
static __device__ float  g_v[NL];       // exp(g)
static __device__ float  g_spart[4*NL]; // cross-block partial sums
static __device__ int    g_ctr[256];    // arrival counters (f-update / k_exp)
static __device__ int    g_ctr2[256];   // arrival counters (g-update)
static __device__ float  g_cnt[NB];
static __device__ float  g_ab[NB];      // a = b = 1/count
static __device__ float  g_cp[NB][3];
static __device__ float  g_ct[NB][3];
static __device__ float  g_R[NB][9];
// Gibbs kernel K = exp(-M) in bf16 pairs, row-major. 67 MB.
static __device__ unsigned int g_K[(size_t)NB * LL * KROW];

#define L2E  1.4426950408889634f
#define LN2  0.6931471805599453f
#define E005 1.0512710963760241f    // exp(0.05) (diag bias: cost -0.1 => M -0.05)

__device__ __forceinline__ float ex2f_(float x){ float r; asm("ex2.approx.ftz.f32 %0,%1;" : "=f"(r) : "f"(x)); return r; }
__device__ __forceinline__ float lg2f_(float x){ float r; asm("lg2.approx.ftz.f32 %0,%1;" : "=f"(r) : "f"(x)); return r; }
__device__ __forceinline__ float bflo(unsigned int k){ return __uint_as_float(k << 16); }
__device__ __forceinline__ float bfhi(unsigned int k){ return __uint_as_float(k & 0xffff0000u); }

// ---------------- prep ----------------
__global__ void k_zero(){ if (threadIdx.x < NB) g_cnt[threadIdx.x] = 0.f; }

__global__ void k_prep(const float* __restrict__ pred, const float* __restrict__ tru,
                       const float* __restrict__ mgen){
    int t = blockIdx.x*256 + threadIdx.x;   // 0..NL-1
    float px = pred[3*t+0], py = pred[3*t+1], pz = pred[3*t+2];
    float qx = tru [3*t+0], qy = tru [3*t+1], qz = tru [3*t+2];
    g_ppack[t] = make_float4(px,py,pz, 0.5f*(px*px+py*py+pz*pz)*L2E);
    g_qpack[t] = make_float4(qx,qy,qz, 0.5f*(qx*qx+qy*qy+qz*qz)*L2E);
    g_v[t] = 1.0f;                          // v = exp(g), g starts at 0
    __shared__ float sred[256];
    sred[threadIdx.x] = (mgen[t] != 0.f) ? 1.f : 0.f;
    __syncthreads();
    for (int s = 128; s > 0; s >>= 1){
        if (threadIdx.x < s) sred[threadIdx.x] += sred[threadIdx.x+s];
        __syncthreads();
    }
    if (threadIdx.x == 0) atomicAdd(&g_cnt[blockIdx.x>>3], sred[0]);  // 8 blocks per batch
}

__global__ void k_prep2(){
    if (threadIdx.x < NB) g_ab[threadIdx.x] = 1.0f / fmaxf(g_cnt[threadIdx.x], 1.f);
}

// ---------------- build K = exp(-M) once + fused first f-update ----------------
// block: 64 rows x 512 cols. warp = row; lane = col pair. (R12 layout: no
// pragma/bounds games — R13 showed those cause spills.)
// Since v0 = 1, u0 = a / rowsum(K); the row sums are accumulated here for
// free while K values are live in registers, finalized via the mvf-style
// g_spart + g_ctr cross-block combine. Saves one k_mvf launch.
__global__ void __launch_bounds__(256) k_exp(){
    __shared__ float4 tile[512];
    __shared__ int lastflag;
    int b = blockIdx.x;
    int qtr = b & 3, rg = b >> 2, n = rg >> 5;
    int row0 = (rg & 31) << 6, c0 = qtr << 9;
    int tid = threadIdx.x, w = tid >> 5, lane = tid & 31;

    for (int i = tid; i < 512; i += 256) tile[i] = g_qpack[n*LL + c0 + i];
    __syncthreads();

    for (int i = 0; i < 8; i++){
        int r = row0 + w + 8*i;
        float4 pp = g_ppack[n*LL + r];
        float px = pp.x*L2E, py = pp.y*L2E, pz = pp.z*L2E, pw = pp.w;
        unsigned int* dst = g_K + ((size_t)n*LL + r)*KROW + (c0 >> 1);
        float acc = 0.f;
        #pragma unroll
        for (int j = 0; j < 8; j++){
            int p = lane + 32*j;             // pair index within 512-col strip
            float4 t0 = tile[2*p], t1 = tile[2*p+1];
            // arg = log2e*(p.q - |p|^2/2 - |q|^2/2) = -M*log2e
            float a0 = fmaf(px,t0.x, fmaf(py,t0.y, fmaf(pz,t0.z, -(pw + t0.w))));
            float a1 = fmaf(px,t1.x, fmaf(py,t1.y, fmaf(pz,t1.z, -(pw + t1.w))));
            float e0 = ex2f_(a0), e1 = ex2f_(a1);
            int gc = c0 + 2*p;
            if (gc     == r) e0 *= E005;     // diag bias folded into K
            if (gc + 1 == r) e1 *= E005;
            acc += e0 + e1;                  // rowsum for u0 (v0 == 1)
            unsigned int kk;
            asm("cvt.rn.bf16x2.f32 %0, %1, %2;" : "=r"(kk) : "f"(e1), "f"(e0));
            dst[p] = kk;                     // low half = col gc, high = gc+1
        }
        #pragma unroll
        for (int o = 16; o; o >>= 1) acc += __shfl_xor_sync(0xFFFFFFFFu, acc, o);
        if (lane == 0) __stcg(&g_spart[qtr*NL + n*LL + r], acc);
    }
    __threadfence();
    __syncthreads();
    if (tid == 0) lastflag = (atomicAdd(&g_ctr[rg], 1) == 3);
    __syncthreads();
    if (lastflag && w < 2){
        int rr = (w << 5) + lane;
        int gidx = n*LL + row0 + rr;
        float S = __ldcg(&g_spart[gidx])
                + __ldcg(&g_spart[NL   + gidx])
                + __ldcg(&g_spart[2*NL + gidx])
                + __ldcg(&g_spart[3*NL + gidx]);
        g_u[gidx] = __fdividef(g_ab[n], fmaxf(S, 1e-35f));
        if (tid == 0) g_ctr[rg] = 0;
    }
}

// ---------------- f half-update: u = a / (K v)  (row-parallel) ----------------
// block: 64 rows x 512 cols; 4 column-quarters combined via g_spart + g_ctr.
__global__ void __launch_bounds__(256) k_mvf(){
    __shared__ float4 vsm[128];              // 512 v values
    __shared__ int lastflag;
    int b = blockIdx.x;
    int qtr = b & 3, rg = b >> 2, n = rg >> 5;
    int row0 = (rg & 31) << 6, c0 = qtr << 9;
    int tid = threadIdx.x, w = tid >> 5, lane = tid & 31;

    float* vf = (float*)vsm;
    for (int i = tid; i < 512; i += 256) vf[i] = g_v[n*LL + c0 + i];
    __syncthreads();

    for (int i = 0; i < 8; i++){
        int r = row0 + w + 8*i;
        const uint2* Kr = (const uint2*)(g_K + ((size_t)n*LL + r)*KROW + (c0 >> 1));
        float acc = 0.f;
        #pragma unroll
        for (int s = 0; s < 4; s++){
            int e = lane + 32*s;             // uint2 = 4 cols; matches vsm[e]
            uint2 kk = Kr[e];
            float4 vv = vsm[e];
            acc = fmaf(bflo(kk.x), vv.x,
                  fmaf(bfhi(kk.x), vv.y,
                  fmaf(bflo(kk.y), vv.z,
                  fmaf(bfhi(kk.y), vv.w, acc))));
        }
        #pragma unroll
        for (int o = 16; o; o >>= 1) acc += __shfl_xor_sync(0xFFFFFFFFu, acc, o);
        if (lane == 0) __stcg(&g_spart[qtr*NL + n*LL + r], acc);
    }
    __threadfence();
    __syncthreads();
    if (tid == 0) lastflag = (atomicAdd(&g_ctr[rg], 1) == 3);
    __syncthreads();
    if (lastflag && w < 2){
        int rr = (w << 5) + lane;
        int gidx = n*LL + row0 + rr;
        float S = __ldcg(&g_spart[gidx])
                + __ldcg(&g_spart[NL   + gidx])
                + __ldcg(&g_spart[2*NL + gidx])
                + __ldcg(&g_spart[3*NL + gidx]);
        g_u[gidx] = __fdividef(g_ab[n], fmaxf(S, 1e-35f));
        if (tid == 0) g_ctr[rg] = 0;
    }
}

// ---------------- g half-update: v = b / (K^T u)  (column-in-register) ------
// block: 512 rows x 64 cols; 4 row-quarters combined via g_spart + g_ctr2.
// K read row-major coalesced (128B per warp-row-step); u broadcast from smem.
__global__ void __launch_bounds__(256) k_mvg(){
    __shared__ float usm[512];
    __shared__ float psum[8][64];
    __shared__ int lastflag;
    int b = blockIdx.x;
    int n = b >> 7, strip = (b >> 2) & 31, rq = b & 3;
    int r0 = rq << 9, c0 = strip << 6;
    int tid = threadIdx.x, cp = tid & 31, rs = tid >> 5;

    for (int i = tid; i < 512; i += 256) usm[i] = g_u[n*LL + r0 + i];
    __syncthreads();

    const unsigned int* Kc = g_K + ((size_t)n*LL + r0)*KROW + (c0 >> 1) + cp;
    float t0 = 0.f, t1 = 0.f;
    #pragma unroll 4
    for (int i = 0; i < 64; i++){
        int lr = rs + 8*i;
        unsigned int kk = Kc[(size_t)lr * KROW];
        float ur = usm[lr];
        t0 = fmaf(bflo(kk), ur, t0);
        t1 = fmaf(bfhi(kk), ur, t1);
    }
    psum[rs][2*cp]   = t0;
    psum[rs][2*cp+1] = t1;
    __syncthreads();
    if (tid < 64){
        float T = 0.f;
        #pragma unroll
        for (int j = 0; j < 8; j++) T += psum[j][tid];
        __stcg(&g_spart[rq*NL + n*LL + c0 + tid], T);
    }
    __threadfence();
    __syncthreads();
    if (tid == 0) lastflag = (atomicAdd(&g_ctr2[n*32 + strip], 1) == 3);
    __syncthreads();
    if (lastflag && tid < 64){
        int gidx = n*LL + c0 + tid;
        float T = __ldcg(&g_spart[gidx])
                + __ldcg(&g_spart[NL   + gidx])
                + __ldcg(&g_spart[2*NL + gidx])
                + __ldcg(&g_spart[3*NL + gidx]);
        g_v[gidx] = __fdividef(g_ab[n], fmaxf(T, 1e-35f));
        if (tid == 0) g_ctr2[n*32 + strip] = 0;
    }
}

// ---------------- pi + true_pos_mapped (full f32 precision) ----------------
// f,g derived inline from u,v: f*L2E = lg2(u), g*L2E = lg2(v).
__global__ void __launch_bounds__(512) k_pi(float* __restrict__ piout, float* __restrict__ tpmout){
    __shared__ float4 tile[LL];
    int n    = blockIdx.x >> 7;          // 128 blocks per batch (16 rows each)
    int row0 = (blockIdx.x & 127) << 4;
    int tid  = threadIdx.x;

    const float4* qp = g_qpack + n*LL;
    const float*  vv = g_v     + n*LL;
    for (int i = tid; i < LL; i += 512){
        float4 c = qp[i];
        c.w = lg2f_(vv[i]) - c.w;        // g*L2E - 0.5|q|^2*L2E
        tile[i] = c;
    }
    __syncthreads();

    int warp = tid >> 5, lane = tid & 31;
    int l = row0 + warp;
    float4 pp = g_ppack[n*LL + l];
    float fp2 = lg2f_(g_u[n*LL + l]) - pp.w;
    float ppx = pp.x*L2E, ppy = pp.y*L2E, ppz = pp.z*L2E;

    float tx=0.f, ty=0.f, tz=0.f;
    float* po = piout + ((size_t)n*LL + l)*LL;
    #pragma unroll 4
    for (int m = lane; m < LL; m += 32){
        float4 c = tile[m];
        float pv = ex2f_(fp2 + fmaf(ppx,c.x, fmaf(ppy,c.y, fmaf(ppz,c.z, c.w))));
        if (m == l) pv *= E005;
        po[m] = pv;
        tx = fmaf(pv, c.x, tx);
        ty = fmaf(pv, c.y, ty);
        tz = fmaf(pv, c.z, tz);
    }
    #pragma unroll
    for (int o = 16; o; o >>= 1){
        tx += __shfl_xor_sync(0xFFFFFFFFu, tx, o);
        ty += __shfl_xor_sync(0xFFFFFFFFu, ty, o);
        tz += __shfl_xor_sync(0xFFFFFFFFu, tz, o);
    }
    if (lane == 0){
        float* tp = tpmout + (size_t)(n*LL + l)*3;
        tp[0] = tx; tp[1] = ty; tp[2] = tz;
    }
}

// ---------------- Kabsch + 3x3 SVD (per batch) ----------------
__global__ void k_kabsch(const float* __restrict__ pred, const float* __restrict__ tpm){
    int n = blockIdx.x, tid = threadIdx.x;
    float s[15];
    #pragma unroll
    for (int k = 0; k < 15; k++) s[k] = 0.f;
    for (int l = tid; l < LL; l += 256){
        const float* p = pred + (size_t)(n*LL + l)*3;
        const float* q = tpm  + (size_t)(n*LL + l)*3;
        float p0=p[0],p1=p[1],p2=p[2], q0=q[0],q1=q[1],q2=q[2];
        s[0]+=p0; s[1]+=p1; s[2]+=p2; s[3]+=q0; s[4]+=q1; s[5]+=q2;
        s[6]+=p0*q0;  s[7]+=p0*q1;  s[8]+=p0*q2;
        s[9]+=p1*q0;  s[10]+=p1*q1; s[11]+=p1*q2;
        s[12]+=p2*q0; s[13]+=p2*q1; s[14]+=p2*q2;
    }
    __shared__ float red[256];
    __shared__ float tot[15];
    for (int k = 0; k < 15; k++){
        red[tid] = s[k]; __syncthreads();
        for (int st = 128; st; st >>= 1){
            if (tid < st) red[tid] += red[tid+st];
            __syncthreads();
        }
        if (tid == 0) tot[k] = red[0];
        __syncthreads();
    }
    if (tid != 0) return;

    double w = fmax((double)g_cnt[n], 1e-6);
    double cp[3] = { tot[0]/w, tot[1]/w, tot[2]/w };
    double cq[3] = { tot[3]/w, tot[4]/w, tot[5]/w };
    double H[3][3];
    for (int i = 0; i < 3; i++)
        for (int j = 0; j < 3; j++)
            H[i][j] = (double)tot[6 + 3*i + j] - w*cp[i]*cq[j];

    double fn = 0.0;
    for (int i = 0; i < 3; i++) for (int j = 0; j < 3; j++) fn += H[i][j]*H[i][j];
    fn = fmax(sqrt(fn), 1e-8);
    double M[3][3];
    for (int i = 0; i < 3; i++)
        for (int j = 0; j < 3; j++)
            M[i][j] = H[i][j]/fn + (i==j ? 1e-4 : 0.0);

    double B[3][3];
    for (int i = 0; i < 3; i++)
        for (int j = 0; j < 3; j++){
            double acc = 0.0;
            for (int k = 0; k < 3; k++) acc += M[k][i]*M[k][j];
            B[i][j] = acc;
        }
    double V[3][3] = {{1,0,0},{0,1,0},{0,0,1}};
    for (int sw = 0; sw < 15; sw++){
        for (int pair = 0; pair < 3; pair++){
            int p = (pair==2) ? 1 : 0;
            int q = (pair==0) ? 1 : 2;
            double apq = B[p][q];
            if (fabs(apq) < 1e-30) continue;
            double tau = (B[q][q] - B[p][p])/(2.0*apq);
            double t = ((tau >= 0.0) ? 1.0 : -1.0)/(fabs(tau) + sqrt(1.0 + tau*tau));
            double c = 1.0/sqrt(1.0 + t*t), sn = t*c;
            for (int k = 0; k < 3; k++){
                double bkp = B[k][p], bkq = B[k][q];
                B[k][p] = c*bkp - sn*bkq; B[k][q] = sn*bkp + c*bkq;
            }
            for (int k = 0; k < 3; k++){
                double bpk = B[p][k], bqk = B[q][k];
                B[p][k] = c*bpk - sn*bqk; B[q][k] = sn*bpk + c*bqk;
            }
            for (int k = 0; k < 3; k++){
                double vkp = V[k][p], vkq = V[k][q];
                V[k][p] = c*vkp - sn*vkq; V[k][q] = sn*vkp + c*vkq;
            }
        }
    }
    double lam[3] = { B[0][0], B[1][1], B[2][2] };
    for (int i = 0; i < 2; i++)
        for (int j = 0; j < 2 - i; j++)
            if (lam[j] < lam[j+1]){
                double tl = lam[j]; lam[j] = lam[j+1]; lam[j+1] = tl;
                for (int k = 0; k < 3; k++){ double tv = V[k][j]; V[k][j] = V[k][j+1]; V[k][j+1] = tv; }
            }
    double detV = V[0][0]*(V[1][1]*V[2][2]-V[1][2]*V[2][1])
                - V[0][1]*(V[1][0]*V[2][2]-V[1][2]*V[2][0])
                + V[0][2]*(V[1][0]*V[2][1]-V[1][1]*V[2][0]);
    if (detV < 0.0) for (int k = 0; k < 3; k++) V[k][2] = -V[k][2];

    double s1 = sqrt(fmax(lam[0], 0.0)), s2 = sqrt(fmax(lam[1], 0.0));
    double u1[3], u2[3], u3[3];
    for (int k = 0; k < 3; k++){
        u1[k] = (M[k][0]*V[0][0] + M[k][1]*V[1][0] + M[k][2]*V[2][0]) / fmax(s1, 1e-30);
        u2[k] = (M[k][0]*V[0][1] + M[k][1]*V[1][1] + M[k][2]*V[2][1]) / fmax(s2, 1e-30);
    }
    double n1 = sqrt(u1[0]*u1[0]+u1[1]*u1[1]+u1[2]*u1[2]);
    for (int k = 0; k < 3; k++) u1[k] /= fmax(n1, 1e-30);
    double d12 = u1[0]*u2[0]+u1[1]*u2[1]+u1[2]*u2[2];
    for (int k = 0; k < 3; k++) u2[k] -= d12*u1[k];
    double n2 = sqrt(u2[0]*u2[0]+u2[1]*u2[1]+u2[2]*u2[2]);
    for (int k = 0; k < 3; k++) u2[k] /= fmax(n2, 1e-30);
    u3[0] = u1[1]*u2[2] - u1[2]*u2[1];
    u3[1] = u1[2]*u2[0] - u1[0]*u2[2];
    u3[2] = u1[0]*u2[1] - u1[1]*u2[0];

    for (int d = 0; d < 3; d++)
        for (int e = 0; e < 3; e++)
            g_R[n][3*d + e] = (float)(u1[d]*V[e][0] + u2[d]*V[e][1] + u3[d]*V[e][2]);
    for (int k = 0; k < 3; k++){ g_cp[n][k] = (float)cp[k]; g_ct[n][k] = (float)cq[k]; }
}

// ---------------- TM score ----------------
__global__ void k_tm(const float* __restrict__ pred, const float* __restrict__ mgen,
                     const float* __restrict__ tpm, float* __restrict__ avg, float inv_d02){
    int n = blockIdx.x, tid = threadIdx.x;
    float R[9];
    #pragma unroll
    for (int k = 0; k < 9; k++) R[k] = g_R[n][k];
    float cp0 = g_cp[n][0], cp1 = g_cp[n][1], cp2 = g_cp[n][2];
    float ct0 = g_ct[n][0], ct1 = g_ct[n][1], ct2 = g_ct[n][2];

    float st = 0.f, sm = 0.f;
    for (int l = tid; l < LL; l += 256){
        const float* p = pred + (size_t)(n*LL + l)*3;
        const float* q = tpm  + (size_t)(n*LL + l)*3;
        float x0 = p[0]-cp0, x1 = p[1]-cp1, x2 = p[2]-cp2;
        float a0 = x0*R[0] + x1*R[3] + x2*R[6] + ct0;
        float a1 = x0*R[1] + x1*R[4] + x2*R[7] + ct1;
        float a2 = x0*R[2] + x1*R[5] + x2*R[8] + ct2;
        float d0 = a0-q[0], d1 = a1-q[1], d2 = a2-q[2];
        float dsq = d0*d0 + d1*d1 + d2*d2;
        float tm = 1.f/(1.f + dsq*inv_d02);
        float mg = mgen[n*LL + l];
        st += tm*mg; sm += mg;
    }
    __shared__ float r1[256], r2[256];
    r1[tid] = st; r2[tid] = sm; __syncthreads();
    for (int s = 128; s; s >>= 1){
        if (tid < s){ r1[tid] += r1[tid+s]; r2[tid] += r2[tid+s]; }
        __syncthreads();
    }
    if (tid == 0) avg[n] = r1[0] / fmaxf(r2[0], 1e-6f);
}

// ---------------- launch ----------------
extern "C" void kernel_launch(void* const* d_in, const int* in_sizes, int n_in,
                              void* d_out, int out_size){
    const float* pred = (const float*)d_in[0];
    const float* tru  = (const float*)d_in[1];
    const float* mgen = (const float*)d_in[2];

    float* out   = (float*)d_out;
    float* avg   = out;                       // (N,)
    float* tpm   = out + NB;                  // (N,L,3)
    float* piout = out + NB + (size_t)NL*3;   // (N,L,L)

    k_zero<<<1, 32>>>();
    k_prep<<<NL/256, 256>>>(pred, tru, mgen);
    k_prep2<<<1, 32>>>();

    k_exp<<<1024, 256>>>();                   // build K + fused first f-update (u0)

    k_mvg<<<1024, 256>>>();                   // it 0 g-update
    for (int it = 1; it < 10; it++){
        k_mvf<<<1024, 256>>>();               // u = a / (K v)
        k_mvg<<<1024, 256>>>();               // v = b / (K^T u)
    }

    k_pi<<<1024, 512>>>(piout, tpm);
    k_kabsch<<<NB, 256>>>(pred, tpm);

    double d0 = 1.24 * cbrt((double)((LL > 16 ? LL : 16) - 15)) - 1.8;
    if (d0 < 0.5) d0 = 0.5;
    float inv_d02 = (float)(1.0/(d0*d0));
    k_tm<<<NB, 256>>>(pred, mgen, tpm, avg, inv_d02);
}

// round 15
// speedup vs baseline: 1.2758x; 1.1220x over previous
#include <cuda_runtime.h>
#include <math.h>
#include <stdint.h>
#include <stddef.h>

#define NB 8
#define LL 2048
#define NL (NB*LL)
#define KROW (LL/2)   // u32 (bf16x2) per K row

// ---------------- device scratch (no allocations allowed) ----------------
static __device__ float4 g_qpack[NL];   // {qx,qy,qz, 0.5*|q|^2 * log2e}
static __device__ float4 g_ppack[NL];   // {px,py,pz, 0.5*|p|^2 * log2e}
static __device__ float  g_u[NL];       // exp(f)
static __device__ float  g_v[NL];       // exp(g)
static __device__ float  g_spart[4*NL]; // cross-block partial sums
static __device__ int    g_ctr[256];    // arrival counters (f-update)
static __device__ int    g_ctr2[256];   // arrival counters (g-update)
static __device__ float  g_cnt[NB];
static __device__ float  g_ab[NB];      // a = b = 1/count
static __device__ float  g_cp[NB][3];
static __device__ float  g_ct[NB][3];
static __device__ float  g_R[NB][9];
// Gibbs kernel K = exp(-M) in bf16 pairs, row-major. 67 MB.
static __device__ unsigned int g_K[(size_t)NB * LL * KROW];

#define L2E  1.4426950408889634f
#define LN2  0.6931471805599453f
#define E005 1.0512710963760241f    // exp(0.05) (diag bias: cost -0.1 => M -0.05)

__device__ __forceinline__ float ex2f_(float x){ float r; asm("ex2.approx.ftz.f32 %0,%1;" : "=f"(r) : "f"(x)); return r; }
__device__ __forceinline__ float lg2f_(float x){ float r; asm("lg2.approx.ftz.f32 %0,%1;" : "=f"(r) : "f"(x)); return r; }
__device__ __forceinline__ float bflo(unsigned int k){ return __uint_as_float(k << 16); }
__device__ __forceinline__ float bfhi(unsigned int k){ return __uint_as_float(k & 0xffff0000u); }

// ---------------- prep ----------------
__global__ void k_zero(){ if (threadIdx.x < NB) g_cnt[threadIdx.x] = 0.f; }

__global__ void k_prep(const float* __restrict__ pred, const float* __restrict__ tru,
                       const float* __restrict__ mgen){
    int t = blockIdx.x*256 + threadIdx.x;   // 0..NL-1
    float px = pred[3*t+0], py = pred[3*t+1], pz = pred[3*t+2];
    float qx = tru [3*t+0], qy = tru [3*t+1], qz = tru [3*t+2];
    g_ppack[t] = make_float4(px,py,pz, 0.5f*(px*px+py*py+pz*pz)*L2E);
    g_qpack[t] = make_float4(qx,qy,qz, 0.5f*(qx*qx+qy*qy+qz*qz)*L2E);
    g_v[t] = 1.0f;                          // v = exp(g), g starts at 0
    __shared__ float sred[256];
    sred[threadIdx.x] = (mgen[t] != 0.f) ? 1.f : 0.f;
    __syncthreads();
    for (int s = 128; s > 0; s >>= 1){
        if (threadIdx.x < s) sred[threadIdx.x] += sred[threadIdx.x+s];
        __syncthreads();
    }
    if (threadIdx.x == 0) atomicAdd(&g_cnt[blockIdx.x>>3], sred[0]);  // 8 blocks per batch
}

__global__ void k_prep2(){
    if (threadIdx.x < NB) g_ab[threadIdx.x] = 1.0f / fmaxf(g_cnt[threadIdx.x], 1.f);
}

// ---------------- build K = exp(-M) once (bf16, row-major) ----------------
// FROZEN R12 formulation (regs=80, 25.4us). Any structural change (bounds
// pragmas, fused reductions) flips ptxas into spill mode — measured 3x.
__global__ void __launch_bounds__(256) k_exp(){
    __shared__ float4 tile[512];
    int b = blockIdx.x;
    int qtr = b & 3, rg = b >> 2, n = rg >> 5;
    int row0 = (rg & 31) << 6, c0 = qtr << 9;
    int tid = threadIdx.x, w = tid >> 5, lane = tid & 31;

    for (int i = tid; i < 512; i += 256) tile[i] = g_qpack[n*LL + c0 + i];
    __syncthreads();

    for (int i = 0; i < 8; i++){
        int r = row0 + w + 8*i;
        float4 pp = g_ppack[n*LL + r];
        float px = pp.x*L2E, py = pp.y*L2E, pz = pp.z*L2E, pw = pp.w;
        unsigned int* dst = g_K + ((size_t)n*LL + r)*KROW + (c0 >> 1);
        #pragma unroll
        for (int j = 0; j < 8; j++){
            int p = lane + 32*j;             // pair index within 512-col strip
            float4 t0 = tile[2*p], t1 = tile[2*p+1];
            // arg = log2e*(p.q - |p|^2/2 - |q|^2/2) = -M*log2e
            float a0 = fmaf(px,t0.x, fmaf(py,t0.y, fmaf(pz,t0.z, -(pw + t0.w))));
            float a1 = fmaf(px,t1.x, fmaf(py,t1.y, fmaf(pz,t1.z, -(pw + t1.w))));
            float e0 = ex2f_(a0), e1 = ex2f_(a1);
            int gc = c0 + 2*p;
            if (gc     == r) e0 *= E005;     // diag bias folded into K
            if (gc + 1 == r) e1 *= E005;
            unsigned int kk;
            asm("cvt.rn.bf16x2.f32 %0, %1, %2;" : "=r"(kk) : "f"(e1), "f"(e0));
            dst[p] = kk;                     // low half = col gc, high = gc+1
        }
    }
}

// ---------------- f half-update: u = a / (K v)  (row-parallel) ----------------
// block: 64 rows x 512 cols; 4 column-quarters combined via g_spart + g_ctr.
// Loop-interchanged vs R12: each v chunk is loaded from smem ONCE and applied
// to all 8 rows (8 accumulators) -> LDS.128 per thread drops 32 -> 4.
__global__ void __launch_bounds__(256) k_mvf(){
    __shared__ float4 vsm[128];              // 512 v values
    __shared__ int lastflag;
    int b = blockIdx.x;
    int qtr = b & 3, rg = b >> 2, n = rg >> 5;
    int row0 = (rg & 31) << 6, c0 = qtr << 9;
    int tid = threadIdx.x, w = tid >> 5, lane = tid & 31;

    float* vf = (float*)vsm;
    for (int i = tid; i < 512; i += 256) vf[i] = g_v[n*LL + c0 + i];
    __syncthreads();

    const unsigned int* Kb = g_K + ((size_t)n*LL + row0 + w)*KROW + (c0 >> 1);
    float acc0=0.f, acc1=0.f, acc2=0.f, acc3=0.f;
    float acc4=0.f, acc5=0.f, acc6=0.f, acc7=0.f;
    #pragma unroll
    for (int s = 0; s < 4; s++){
        int e = lane + 32*s;                 // uint2 = 4 cols; matches vsm[e]
        float4 vv = vsm[e];
        #pragma unroll
        for (int i = 0; i < 8; i++){
            uint2 kk = ((const uint2*)(Kb + (size_t)(8*i)*KROW))[e];
            float t = fmaf(bflo(kk.x), vv.x,
                      fmaf(bfhi(kk.x), vv.y,
                      fmaf(bflo(kk.y), vv.z,
                           bfhi(kk.y) * vv.w)));
            if (i == 0) acc0 += t;
            if (i == 1) acc1 += t;
            if (i == 2) acc2 += t;
            if (i == 3) acc3 += t;
            if (i == 4) acc4 += t;
            if (i == 5) acc5 += t;
            if (i == 6) acc6 += t;
            if (i == 7) acc7 += t;
        }
    }
    #pragma unroll
    for (int i = 0; i < 8; i++){
        float acc = (i==0)?acc0:(i==1)?acc1:(i==2)?acc2:(i==3)?acc3:
                    (i==4)?acc4:(i==5)?acc5:(i==6)?acc6:acc7;
        #pragma unroll
        for (int o = 16; o; o >>= 1) acc += __shfl_xor_sync(0xFFFFFFFFu, acc, o);
        if (lane == 0) __stcg(&g_spart[qtr*NL + n*LL + row0 + w + 8*i], acc);
    }
    __threadfence();
    __syncthreads();
    if (tid == 0) lastflag = (atomicAdd(&g_ctr[rg], 1) == 3);
    __syncthreads();
    if (lastflag && w < 2){
        int rr = (w << 5) + lane;
        int gidx = n*LL + row0 + rr;
        float S = __ldcg(&g_spart[gidx])
                + __ldcg(&g_spart[NL   + gidx])
                + __ldcg(&g_spart[2*NL + gidx])
                + __ldcg(&g_spart[3*NL + gidx]);
        g_u[gidx] = __fdividef(g_ab[n], fmaxf(S, 1e-35f));
        if (tid == 0) g_ctr[rg] = 0;
    }
}

// ---------------- g half-update: v = b / (K^T u)  (column-in-register) ------
// block: 512 rows x 64 cols; 4 row-quarters combined via g_spart + g_ctr2.
// K read row-major coalesced (128B per warp-row-step); u broadcast from smem.
__global__ void __launch_bounds__(256) k_mvg(){
    __shared__ float usm[512];
    __shared__ float psum[8][64];
    __shared__ int lastflag;
    int b = blockIdx.x;
    int n = b >> 7, strip = (b >> 2) & 31, rq = b & 3;
    int r0 = rq << 9, c0 = strip << 6;
    int tid = threadIdx.x, cp = tid & 31, rs = tid >> 5;

    for (int i = tid; i < 512; i += 256) usm[i] = g_u[n*LL + r0 + i];
    __syncthreads();

    const unsigned int* Kc = g_K + ((size_t)n*LL + r0)*KROW + (c0 >> 1) + cp;
    float t0 = 0.f, t1 = 0.f;
    #pragma unroll 4
    for (int i = 0; i < 64; i++){
        int lr = rs + 8*i;
        unsigned int kk = Kc[(size_t)lr * KROW];
        float ur = usm[lr];
        t0 = fmaf(bflo(kk), ur, t0);
        t1 = fmaf(bfhi(kk), ur, t1);
    }
    psum[rs][2*cp]   = t0;
    psum[rs][2*cp+1] = t1;
    __syncthreads();
    if (tid < 64){
        float T = 0.f;
        #pragma unroll
        for (int j = 0; j < 8; j++) T += psum[j][tid];
        __stcg(&g_spart[rq*NL + n*LL + c0 + tid], T);
    }
    __threadfence();
    __syncthreads();
    if (tid == 0) lastflag = (atomicAdd(&g_ctr2[n*32 + strip], 1) == 3);
    __syncthreads();
    if (lastflag && tid < 64){
        int gidx = n*LL + c0 + tid;
        float T = __ldcg(&g_spart[gidx])
                + __ldcg(&g_spart[NL   + gidx])
                + __ldcg(&g_spart[2*NL + gidx])
                + __ldcg(&g_spart[3*NL + gidx]);
        g_v[gidx] = __fdividef(g_ab[n], fmaxf(T, 1e-35f));
        if (tid == 0) g_ctr2[n*32 + strip] = 0;
    }
}

// ---------------- pi + true_pos_mapped (full f32 precision) ----------------
// f,g derived inline from u,v: f*L2E = lg2(u), g*L2E = lg2(v).
__global__ void __launch_bounds__(512) k_pi(float* __restrict__ piout, float* __restrict__ tpmout){
    __shared__ float4 tile[LL];
    int n    = blockIdx.x >> 7;          // 128 blocks per batch (16 rows each)
    int row0 = (blockIdx.x & 127) << 4;
    int tid  = threadIdx.x;

    const float4* qp = g_qpack + n*LL;
    const float*  vv = g_v     + n*LL;
    for (int i = tid; i < LL; i += 512){
        float4 c = qp[i];
        c.w = lg2f_(vv[i]) - c.w;        // g*L2E - 0.5|q|^2*L2E
        tile[i] = c;
    }
    __syncthreads();

    int warp = tid >> 5, lane = tid & 31;
    int l = row0 + warp;
    float4 pp = g_ppack[n*LL + l];
    float fp2 = lg2f_(g_u[n*LL + l]) - pp.w;
    float ppx = pp.x*L2E, ppy = pp.y*L2E, ppz = pp.z*L2E;

    float tx=0.f, ty=0.f, tz=0.f;
    float* po = piout + ((size_t)n*LL + l)*LL;
    #pragma unroll 4
    for (int m = lane; m < LL; m += 32){
        float4 c = tile[m];
        float pv = ex2f_(fp2 + fmaf(ppx,c.x, fmaf(ppy,c.y, fmaf(ppz,c.z, c.w))));
        if (m == l) pv *= E005;
        po[m] = pv;
        tx = fmaf(pv, c.x, tx);
        ty = fmaf(pv, c.y, ty);
        tz = fmaf(pv, c.z, tz);
    }
    #pragma unroll
    for (int o = 16; o; o >>= 1){
        tx += __shfl_xor_sync(0xFFFFFFFFu, tx, o);
        ty += __shfl_xor_sync(0xFFFFFFFFu, ty, o);
        tz += __shfl_xor_sync(0xFFFFFFFFu, tz, o);
    }
    if (lane == 0){
        float* tp = tpmout + (size_t)(n*LL + l)*3;
        tp[0] = tx; tp[1] = ty; tp[2] = tz;
    }
}

// ---------------- Kabsch + 3x3 SVD (per batch) ----------------
__global__ void k_kabsch(const float* __restrict__ pred, const float* __restrict__ tpm){
    int n = blockIdx.x, tid = threadIdx.x;
    float s[15];
    #pragma unroll
    for (int k = 0; k < 15; k++) s[k] = 0.f;
    for (int l = tid; l < LL; l += 256){
        const float* p = pred + (size_t)(n*LL + l)*3;
        const float* q = tpm  + (size_t)(n*LL + l)*3;
        float p0=p[0],p1=p[1],p2=p[2], q0=q[0],q1=q[1],q2=q[2];
        s[0]+=p0; s[1]+=p1; s[2]+=p2; s[3]+=q0; s[4]+=q1; s[5]+=q2;
        s[6]+=p0*q0;  s[7]+=p0*q1;  s[8]+=p0*q2;
        s[9]+=p1*q0;  s[10]+=p1*q1; s[11]+=p1*q2;
        s[12]+=p2*q0; s[13]+=p2*q1; s[14]+=p2*q2;
    }
    __shared__ float red[256];
    __shared__ float tot[15];
    for (int k = 0; k < 15; k++){
        red[tid] = s[k]; __syncthreads();
        for (int st = 128; st; st >>= 1){
            if (tid < st) red[tid] += red[tid+st];
            __syncthreads();
        }
        if (tid == 0) tot[k] = red[0];
        __syncthreads();
    }
    if (tid != 0) return;

    double w = fmax((double)g_cnt[n], 1e-6);
    double cp[3] = { tot[0]/w, tot[1]/w, tot[2]/w };
    double cq[3] = { tot[3]/w, tot[4]/w, tot[5]/w };
    double H[3][3];
    for (int i = 0; i < 3; i++)
        for (int j = 0; j < 3; j++)
            H[i][j] = (double)tot[6 + 3*i + j] - w*cp[i]*cq[j];

    double fn = 0.0;
    for (int i = 0; i < 3; i++) for (int j = 0; j < 3; j++) fn += H[i][j]*H[i][j];
    fn = fmax(sqrt(fn), 1e-8);
    double M[3][3];
    for (int i = 0; i < 3; i++)
        for (int j = 0; j < 3; j++)
            M[i][j] = H[i][j]/fn + (i==j ? 1e-4 : 0.0);

    double B[3][3];
    for (int i = 0; i < 3; i++)
        for (int j = 0; j < 3; j++){
            double acc = 0.0;
            for (int k = 0; k < 3; k++) acc += M[k][i]*M[k][j];
            B[i][j] = acc;
        }
    double V[3][3] = {{1,0,0},{0,1,0},{0,0,1}};
    for (int sw = 0; sw < 15; sw++){
        for (int pair = 0; pair < 3; pair++){
            int p = (pair==2) ? 1 : 0;
            int q = (pair==0) ? 1 : 2;
            double apq = B[p][q];
            if (fabs(apq) < 1e-30) continue;
            double tau = (B[q][q] - B[p][p])/(2.0*apq);
            double t = ((tau >= 0.0) ? 1.0 : -1.0)/(fabs(tau) + sqrt(1.0 + tau*tau));
            double c = 1.0/sqrt(1.0 + t*t), sn = t*c;
            for (int k = 0; k < 3; k++){
                double bkp = B[k][p], bkq = B[k][q];
                B[k][p] = c*bkp - sn*bkq; B[k][q] = sn*bkp + c*bkq;
            }
            for (int k = 0; k < 3; k++){
                double bpk = B[p][k], bqk = B[q][k];
                B[p][k] = c*bpk - sn*bqk; B[q][k] = sn*bpk + c*bqk;
            }
            for (int k = 0; k < 3; k++){
                double vkp = V[k][p], vkq = V[k][q];
                V[k][p] = c*vkp - sn*vkq; V[k][q] = sn*vkp + c*vkq;
            }
        }
    }
    double lam[3] = { B[0][0], B[1][1], B[2][2] };
    for (int i = 0; i < 2; i++)
        for (int j = 0; j < 2 - i; j++)
            if (lam[j] < lam[j+1]){
                double tl = lam[j]; lam[j] = lam[j+1]; lam[j+1] = tl;
                for (int k = 0; k < 3; k++){ double tv = V[k][j]; V[k][j] = V[k][j+1]; V[k][j+1] = tv; }
            }
    double detV = V[0][0]*(V[1][1]*V[2][2]-V[1][2]*V[2][1])
                - V[0][1]*(V[1][0]*V[2][2]-V[1][2]*V[2][0])
                + V[0][2]*(V[1][0]*V[2][1]-V[1][1]*V[2][0]);
    if (detV < 0.0) for (int k = 0; k < 3; k++) V[k][2] = -V[k][2];

    double s1 = sqrt(fmax(lam[0], 0.0)), s2 = sqrt(fmax(lam[1], 0.0));
    double u1[3], u2[3], u3[3];
    for (int k = 0; k < 3; k++){
        u1[k] = (M[k][0]*V[0][0] + M[k][1]*V[1][0] + M[k][2]*V[2][0]) / fmax(s1, 1e-30);
        u2[k] = (M[k][0]*V[0][1] + M[k][1]*V[1][1] + M[k][2]*V[2][1]) / fmax(s2, 1e-30);
    }
    double n1 = sqrt(u1[0]*u1[0]+u1[1]*u1[1]+u1[2]*u1[2]);
    for (int k = 0; k < 3; k++) u1[k] /= fmax(n1, 1e-30);
    double d12 = u1[0]*u2[0]+u1[1]*u2[1]+u1[2]*u2[2];
    for (int k = 0; k < 3; k++) u2[k] -= d12*u1[k];
    double n2 = sqrt(u2[0]*u2[0]+u2[1]*u2[1]+u2[2]*u2[2]);
    for (int k = 0; k < 3; k++) u2[k] /= fmax(n2, 1e-30);
    u3[0] = u1[1]*u2[2] - u1[2]*u2[1];
    u3[1] = u1[2]*u2[0] - u1[0]*u2[2];
    u3[2] = u1[0]*u2[1] - u1[1]*u2[0];

    for (int d = 0; d < 3; d++)
        for (int e = 0; e < 3; e++)
            g_R[n][3*d + e] = (float)(u1[d]*V[e][0] + u2[d]*V[e][1] + u3[d]*V[e][2]);
    for (int k = 0; k < 3; k++){ g_cp[n][k] = (float)cp[k]; g_ct[n][k] = (float)cq[k]; }
}

// ---------------- TM score ----------------
__global__ void k_tm(const float* __restrict__ pred, const float* __restrict__ mgen,
                     const float* __restrict__ tpm, float* __restrict__ avg, float inv_d02){
    int n = blockIdx.x, tid = threadIdx.x;
    float R[9];
    #pragma unroll
    for (int k = 0; k < 9; k++) R[k] = g_R[n][k];
    float cp0 = g_cp[n][0], cp1 = g_cp[n][1], cp2 = g_cp[n][2];
    float ct0 = g_ct[n][0], ct1 = g_ct[n][1], ct2 = g_ct[n][2];

    float st = 0.f, sm = 0.f;
    for (int l = tid; l < LL; l += 256){
        const float* p = pred + (size_t)(n*LL + l)*3;
        const float* q = tpm  + (size_t)(n*LL + l)*3;
        float x0 = p[0]-cp0, x1 = p[1]-cp1, x2 = p[2]-cp2;
        float a0 = x0*R[0] + x1*R[3] + x2*R[6] + ct0;
        float a1 = x0*R[1] + x1*R[4] + x2*R[7] + ct1;
        float a2 = x0*R[2] + x1*R[5] + x2*R[8] + ct2;
        float d0 = a0-q[0], d1 = a1-q[1], d2 = a2-q[2];
        float dsq = d0*d0 + d1*d1 + d2*d2;
        float tm = 1.f/(1.f + dsq*inv_d02);
        float mg = mgen[n*LL + l];
        st += tm*mg; sm += mg;
    }
    __shared__ float r1[256], r2[256];
    r1[tid] = st; r2[tid] = sm; __syncthreads();
    for (int s = 128; s; s >>= 1){
        if (tid < s){ r1[tid] += r1[tid+s]; r2[tid] += r2[tid+s]; }
        __syncthreads();
    }
    if (tid == 0) avg[n] = r1[0] / fmaxf(r2[0], 1e-6f);
}

// ---------------- launch ----------------
extern "C" void kernel_launch(void* const* d_in, const int* in_sizes, int n_in,
                              void* d_out, int out_size){
    const float* pred = (const float*)d_in[0];
    const float* tru  = (const float*)d_in[1];
    const float* mgen = (const float*)d_in[2];

    float* out   = (float*)d_out;
    float* avg   = out;                       // (N,)
    float* tpm   = out + NB;                  // (N,L,3)
    float* piout = out + NB + (size_t)NL*3;   // (N,L,L)

    k_zero<<<1, 32>>>();
    k_prep<<<NL/256, 256>>>(pred, tru, mgen);
    k_prep2<<<1, 32>>>();

    k_exp<<<1024, 256>>>();                   // build K once (only exp-heavy pass)

    for (int it = 0; it < 10; it++){
        k_mvf<<<1024, 256>>>();               // u = a / (K v)
        k_mvg<<<1024, 256>>>();               // v = b / (K^T u)
    }

    k_pi<<<1024, 512>>>(piout, tpm);
    k_kabsch<<<NB, 256>>>(pred, tpm);

    double d0 = 1.24 * cbrt((double)((LL > 16 ? LL : 16) - 15)) - 1.8;
    if (d0 < 0.5) d0 = 0.5;
    float inv_d02 = (float)(1.0/(d0*d0));
    k_tm<<<NB, 256>>>(pred, mgen, tpm, avg, inv_d02);
}

// round 16
// speedup vs baseline: 1.3808x; 1.0824x over previous
#include <cuda_runtime.h>
#include <math.h>
#include <stdint.h>
#include <stddef.h>

#define NB 8
#define LL 2048
#define NL (NB*LL)
#define KROW (LL/2)   // u32 (bf16x2) per K row

// ---------------- device scratch (no allocations allowed) ----------------
static __device__ float4 g_qpack[NL];   // {qx,qy,qz, 0.5*|q|^2 * log2e}
static __device__ float4 g_ppack[NL];   // {px,py,pz, 0.5*|p|^2 * log2e}
static __device__ float  g_u[NL];       // exp(f)
static __device__ float  g_v[NL];       // exp(g)
static __device__ float  g_spart[8*NL]; // cross-block partial sums (mvf uses 4, mvg uses 8)
static __device__ int    g_ctr[256];    // arrival counters (f-update)
static __device__ int    g_ctr2[256];   // arrival counters (g-update)
static __device__ float  g_cnt[NB];
static __device__ float  g_ab[NB];      // a = b = 1/count
static __device__ float  g_cp[NB][3];
static __device__ float  g_ct[NB][3];
static __device__ float  g_R[NB][9];
// Gibbs kernel K = exp(-M) in bf16 pairs, row-major. 67 MB.
static __device__ unsigned int g_K[(size_t)NB * LL * KROW];

#define L2E  1.4426950408889634f
#define LN2  0.6931471805599453f
#define E005 1.0512710963760241f    // exp(0.05) (diag bias: cost -0.1 => M -0.05)

__device__ __forceinline__ float ex2f_(float x){ float r; asm("ex2.approx.ftz.f32 %0,%1;" : "=f"(r) : "f"(x)); return r; }
__device__ __forceinline__ float lg2f_(float x){ float r; asm("lg2.approx.ftz.f32 %0,%1;" : "=f"(r) : "f"(x)); return r; }
__device__ __forceinline__ float bflo(unsigned int k){ return __uint_as_float(k << 16); }
__device__ __forceinline__ float bfhi(unsigned int k){ return __uint_as_float(k & 0xffff0000u); }

// ---------------- prep ----------------
__global__ void k_zero(){ if (threadIdx.x < NB) g_cnt[threadIdx.x] = 0.f; }

__global__ void k_prep(const float* __restrict__ pred, const float* __restrict__ tru,
                       const float* __restrict__ mgen){
    int t = blockIdx.x*256 + threadIdx.x;   // 0..NL-1
    float px = pred[3*t+0], py = pred[3*t+1], pz = pred[3*t+2];
    float qx = tru [3*t+0], qy = tru [3*t+1], qz = tru [3*t+2];
    g_ppack[t] = make_float4(px,py,pz, 0.5f*(px*px+py*py+pz*pz)*L2E);
    g_qpack[t] = make_float4(qx,qy,qz, 0.5f*(qx*qx+qy*qy+qz*qz)*L2E);
    g_v[t] = 1.0f;                          // v = exp(g), g starts at 0
    __shared__ float sred[256];
    sred[threadIdx.x] = (mgen[t] != 0.f) ? 1.f : 0.f;
    __syncthreads();
    for (int s = 128; s > 0; s >>= 1){
        if (threadIdx.x < s) sred[threadIdx.x] += sred[threadIdx.x+s];
        __syncthreads();
    }
    if (threadIdx.x == 0) atomicAdd(&g_cnt[blockIdx.x>>3], sred[0]);  // 8 blocks per batch
}

__global__ void k_prep2(){
    if (threadIdx.x < NB) g_ab[threadIdx.x] = 1.0f / fmaxf(g_cnt[threadIdx.x], 1.f);
}

// ---------------- build K = exp(-M) once (bf16, row-major) ----------------
// FROZEN R12 formulation (regs=80, 25.4us). Any structural change (bounds
// pragmas, fused reductions) flips ptxas into spill mode — measured 3x.
__global__ void __launch_bounds__(256) k_exp(){
    __shared__ float4 tile[512];
    int b = blockIdx.x;
    int qtr = b & 3, rg = b >> 2, n = rg >> 5;
    int row0 = (rg & 31) << 6, c0 = qtr << 9;
    int tid = threadIdx.x, w = tid >> 5, lane = tid & 31;

    for (int i = tid; i < 512; i += 256) tile[i] = g_qpack[n*LL + c0 + i];
    __syncthreads();

    for (int i = 0; i < 8; i++){
        int r = row0 + w + 8*i;
        float4 pp = g_ppack[n*LL + r];
        float px = pp.x*L2E, py = pp.y*L2E, pz = pp.z*L2E, pw = pp.w;
        unsigned int* dst = g_K + ((size_t)n*LL + r)*KROW + (c0 >> 1);
        #pragma unroll
        for (int j = 0; j < 8; j++){
            int p = lane + 32*j;             // pair index within 512-col strip
            float4 t0 = tile[2*p], t1 = tile[2*p+1];
            // arg = log2e*(p.q - |p|^2/2 - |q|^2/2) = -M*log2e
            float a0 = fmaf(px,t0.x, fmaf(py,t0.y, fmaf(pz,t0.z, -(pw + t0.w))));
            float a1 = fmaf(px,t1.x, fmaf(py,t1.y, fmaf(pz,t1.z, -(pw + t1.w))));
            float e0 = ex2f_(a0), e1 = ex2f_(a1);
            int gc = c0 + 2*p;
            if (gc     == r) e0 *= E005;     // diag bias folded into K
            if (gc + 1 == r) e1 *= E005;
            unsigned int kk;
            asm("cvt.rn.bf16x2.f32 %0, %1, %2;" : "=r"(kk) : "f"(e1), "f"(e0));
            dst[p] = kk;                     // low half = col gc, high = gc+1
        }
    }
}

// ---------------- f half-update: u = a / (K v)  (row-parallel) ----------------
// FROZEN R15 formulation (loop-interchanged, ~8.8us).
__global__ void __launch_bounds__(256) k_mvf(){
    __shared__ float4 vsm[128];              // 512 v values
    __shared__ int lastflag;
    int b = blockIdx.x;
    int qtr = b & 3, rg = b >> 2, n = rg >> 5;
    int row0 = (rg & 31) << 6, c0 = qtr << 9;
    int tid = threadIdx.x, w = tid >> 5, lane = tid & 31;

    float* vf = (float*)vsm;
    for (int i = tid; i < 512; i += 256) vf[i] = g_v[n*LL + c0 + i];
    __syncthreads();

    const unsigned int* Kb = g_K + ((size_t)n*LL + row0 + w)*KROW + (c0 >> 1);
    float acc0=0.f, acc1=0.f, acc2=0.f, acc3=0.f;
    float acc4=0.f, acc5=0.f, acc6=0.f, acc7=0.f;
    #pragma unroll
    for (int s = 0; s < 4; s++){
        int e = lane + 32*s;                 // uint2 = 4 cols; matches vsm[e]
        float4 vv = vsm[e];
        #pragma unroll
        for (int i = 0; i < 8; i++){
            uint2 kk = ((const uint2*)(Kb + (size_t)(8*i)*KROW))[e];
            float t = fmaf(bflo(kk.x), vv.x,
                      fmaf(bfhi(kk.x), vv.y,
                      fmaf(bflo(kk.y), vv.z,
                           bfhi(kk.y) * vv.w)));
            if (i == 0) acc0 += t;
            if (i == 1) acc1 += t;
            if (i == 2) acc2 += t;
            if (i == 3) acc3 += t;
            if (i == 4) acc4 += t;
            if (i == 5) acc5 += t;
            if (i == 6) acc6 += t;
            if (i == 7) acc7 += t;
        }
    }
    #pragma unroll
    for (int i = 0; i < 8; i++){
        float acc = (i==0)?acc0:(i==1)?acc1:(i==2)?acc2:(i==3)?acc3:
                    (i==4)?acc4:(i==5)?acc5:(i==6)?acc6:acc7;
        #pragma unroll
        for (int o = 16; o; o >>= 1) acc += __shfl_xor_sync(0xFFFFFFFFu, acc, o);
        if (lane == 0) __stcg(&g_spart[qtr*NL + n*LL + row0 + w + 8*i], acc);
    }
    __threadfence();
    __syncthreads();
    if (tid == 0) lastflag = (atomicAdd(&g_ctr[rg], 1) == 3);
    __syncthreads();
    if (lastflag && w < 2){
        int rr = (w << 5) + lane;
        int gidx = n*LL + row0 + rr;
        float S = __ldcg(&g_spart[gidx])
                + __ldcg(&g_spart[NL   + gidx])
                + __ldcg(&g_spart[2*NL + gidx])
                + __ldcg(&g_spart[3*NL + gidx]);
        g_u[gidx] = __fdividef(g_ab[n], fmaxf(S, 1e-35f));
        if (tid == 0) g_ctr[rg] = 0;
    }
}

// ---------------- g half-update: v = b / (K^T u)  (column-in-register) ------
// R16 re-tile: block = 256 rows x 128 cols (uint2 loads: 4 cols/lane).
// grid = 8 batches x 16 col-strips x 8 row-eighths = 1024.
// LDG per thread: 32 x LDG.64 (was 64 x LDG.32); LDS halved too.
__global__ void __launch_bounds__(256) k_mvg(){
    __shared__ float usm[256];
    __shared__ float psum[8][128];
    __shared__ int lastflag;
    int b = blockIdx.x;
    int n = b >> 7, strip = (b >> 3) & 15, re = b & 7;
    int r0 = re << 8;                        // 256 rows per eighth
    int c0 = strip << 7;                     // 128 cols per strip
    int tid = threadIdx.x, cp = tid & 31, rs = tid >> 5;

    for (int i = tid; i < 256; i += 256) usm[i] = g_u[n*LL + r0 + i];
    __syncthreads();

    const unsigned int* Kbase = g_K + ((size_t)n*LL + r0)*KROW + (c0 >> 1) + 2*cp;
    float t0 = 0.f, t1 = 0.f, t2 = 0.f, t3 = 0.f;
    #pragma unroll 4
    for (int i = 0; i < 32; i++){
        int lr = rs + 8*i;
        uint2 kk = *(const uint2*)(Kbase + (size_t)lr * KROW);
        float ur = usm[lr];
        t0 = fmaf(bflo(kk.x), ur, t0);
        t1 = fmaf(bfhi(kk.x), ur, t1);
        t2 = fmaf(bflo(kk.y), ur, t2);
        t3 = fmaf(bfhi(kk.y), ur, t3);
    }
    psum[rs][4*cp+0] = t0;
    psum[rs][4*cp+1] = t1;
    psum[rs][4*cp+2] = t2;
    psum[rs][4*cp+3] = t3;
    __syncthreads();
    if (tid < 128){
        float T = 0.f;
        #pragma unroll
        for (int j = 0; j < 8; j++) T += psum[j][tid];
        __stcg(&g_spart[re*NL + n*LL + c0 + tid], T);
    }
    __threadfence();
    __syncthreads();
    if (tid == 0) lastflag = (atomicAdd(&g_ctr2[n*16 + strip], 1) == 7);
    __syncthreads();
    if (lastflag && tid < 128){
        int gidx = n*LL + c0 + tid;
        float T = 0.f;
        #pragma unroll
        for (int k = 0; k < 8; k++) T += __ldcg(&g_spart[k*NL + gidx]);
        g_v[gidx] = __fdividef(g_ab[n], fmaxf(T, 1e-35f));
        if (tid == 0) g_ctr2[n*16 + strip] = 0;
    }
}

// ---------------- pi + true_pos_mapped (full f32 precision) ----------------
// f,g derived inline from u,v: f*L2E = lg2(u), g*L2E = lg2(v).
__global__ void __launch_bounds__(512) k_pi(float* __restrict__ piout, float* __restrict__ tpmout){
    __shared__ float4 tile[LL];
    int n    = blockIdx.x >> 7;          // 128 blocks per batch (16 rows each)
    int row0 = (blockIdx.x & 127) << 4;
    int tid  = threadIdx.x;

    const float4* qp = g_qpack + n*LL;
    const float*  vv = g_v     + n*LL;
    for (int i = tid; i < LL; i += 512){
        float4 c = qp[i];
        c.w = lg2f_(vv[i]) - c.w;        // g*L2E - 0.5|q|^2*L2E
        tile[i] = c;
    }
    __syncthreads();

    int warp = tid >> 5, lane = tid & 31;
    int l = row0 + warp;
    float4 pp = g_ppack[n*LL + l];
    float fp2 = lg2f_(g_u[n*LL + l]) - pp.w;
    float ppx = pp.x*L2E, ppy = pp.y*L2E, ppz = pp.z*L2E;

    float tx=0.f, ty=0.f, tz=0.f;
    float* po = piout + ((size_t)n*LL + l)*LL;
    #pragma unroll 4
    for (int m = lane; m < LL; m += 32){
        float4 c = tile[m];
        float pv = ex2f_(fp2 + fmaf(ppx,c.x, fmaf(ppy,c.y, fmaf(ppz,c.z, c.w))));
        if (m == l) pv *= E005;
        po[m] = pv;
        tx = fmaf(pv, c.x, tx);
        ty = fmaf(pv, c.y, ty);
        tz = fmaf(pv, c.z, tz);
    }
    #pragma unroll
    for (int o = 16; o; o >>= 1){
        tx += __shfl_xor_sync(0xFFFFFFFFu, tx, o);
        ty += __shfl_xor_sync(0xFFFFFFFFu, ty, o);
        tz += __shfl_xor_sync(0xFFFFFFFFu, tz, o);
    }
    if (lane == 0){
        float* tp = tpmout + (size_t)(n*LL + l)*3;
        tp[0] = tx; tp[1] = ty; tp[2] = tz;
    }
}

// ---------------- Kabsch + 3x3 SVD (per batch) ----------------
__global__ void k_kabsch(const float* __restrict__ pred, const float* __restrict__ tpm){
    int n = blockIdx.x, tid = threadIdx.x;
    float s[15];
    #pragma unroll
    for (int k = 0; k < 15; k++) s[k] = 0.f;
    for (int l = tid; l < LL; l += 256){
        const float* p = pred + (size_t)(n*LL + l)*3;
        const float* q = tpm  + (size_t)(n*LL + l)*3;
        float p0=p[0],p1=p[1],p2=p[2], q0=q[0],q1=q[1],q2=q[2];
        s[0]+=p0; s[1]+=p1; s[2]+=p2; s[3]+=q0; s[4]+=q1; s[5]+=q2;
        s[6]+=p0*q0;  s[7]+=p0*q1;  s[8]+=p0*q2;
        s[9]+=p1*q0;  s[10]+=p1*q1; s[11]+=p1*q2;
        s[12]+=p2*q0; s[13]+=p2*q1; s[14]+=p2*q2;
    }
    __shared__ float red[256];
    __shared__ float tot[15];
    for (int k = 0; k < 15; k++){
        red[tid] = s[k]; __syncthreads();
        for (int st = 128; st; st >>= 1){
            if (tid < st) red[tid] += red[tid+st];
            __syncthreads();
        }
        if (tid == 0) tot[k] = red[0];
        __syncthreads();
    }
    if (tid != 0) return;

    double w = fmax((double)g_cnt[n], 1e-6);
    double cp[3] = { tot[0]/w, tot[1]/w, tot[2]/w };
    double cq[3] = { tot[3]/w, tot[4]/w, tot[5]/w };
    double H[3][3];
    for (int i = 0; i < 3; i++)
        for (int j = 0; j < 3; j++)
            H[i][j] = (double)tot[6 + 3*i + j] - w*cp[i]*cq[j];

    double fn = 0.0;
    for (int i = 0; i < 3; i++) for (int j = 0; j < 3; j++) fn += H[i][j]*H[i][j];
    fn = fmax(sqrt(fn), 1e-8);
    double M[3][3];
    for (int i = 0; i < 3; i++)
        for (int j = 0; j < 3; j++)
            M[i][j] = H[i][j]/fn + (i==j ? 1e-4 : 0.0);

    double B[3][3];
    for (int i = 0; i < 3; i++)
        for (int j = 0; j < 3; j++){
            double acc = 0.0;
            for (int k = 0; k < 3; k++) acc += M[k][i]*M[k][j];
            B[i][j] = acc;
        }
    double V[3][3] = {{1,0,0},{0,1,0},{0,0,1}};
    for (int sw = 0; sw < 15; sw++){
        for (int pair = 0; pair < 3; pair++){
            int p = (pair==2) ? 1 : 0;
            int q = (pair==0) ? 1 : 2;
            double apq = B[p][q];
            if (fabs(apq) < 1e-30) continue;
            double tau = (B[q][q] - B[p][p])/(2.0*apq);
            double t = ((tau >= 0.0) ? 1.0 : -1.0)/(fabs(tau) + sqrt(1.0 + tau*tau));
            double c = 1.0/sqrt(1.0 + t*t), sn = t*c;
            for (int k = 0; k < 3; k++){
                double bkp = B[k][p], bkq = B[k][q];
                B[k][p] = c*bkp - sn*bkq; B[k][q] = sn*bkp + c*bkq;
            }
            for (int k = 0; k < 3; k++){
                double bpk = B[p][k], bqk = B[q][k];
                B[p][k] = c*bpk - sn*bqk; B[q][k] = sn*bpk + c*bqk;
            }
            for (int k = 0; k < 3; k++){
                double vkp = V[k][p], vkq = V[k][q];
                V[k][p] = c*vkp - sn*vkq; V[k][q] = sn*vkp + c*vkq;
            }
        }
    }
    double lam[3] = { B[0][0], B[1][1], B[2][2] };
    for (int i = 0; i < 2; i++)
        for (int j = 0; j < 2 - i; j++)
            if (lam[j] < lam[j+1]){
                double tl = lam[j]; lam[j] = lam[j+1]; lam[j+1] = tl;
                for (int k = 0; k < 3; k++){ double tv = V[k][j]; V[k][j] = V[k][j+1]; V[k][j+1] = tv; }
            }
    double detV = V[0][0]*(V[1][1]*V[2][2]-V[1][2]*V[2][1])
                - V[0][1]*(V[1][0]*V[2][2]-V[1][2]*V[2][0])
                + V[0][2]*(V[1][0]*V[2][1]-V[1][1]*V[2][0]);
    if (detV < 0.0) for (int k = 0; k < 3; k++) V[k][2] = -V[k][2];

    double s1 = sqrt(fmax(lam[0], 0.0)), s2 = sqrt(fmax(lam[1], 0.0));
    double u1[3], u2[3], u3[3];
    for (int k = 0; k < 3; k++){
        u1[k] = (M[k][0]*V[0][0] + M[k][1]*V[1][0] + M[k][2]*V[2][0]) / fmax(s1, 1e-30);
        u2[k] = (M[k][0]*V[0][1] + M[k][1]*V[1][1] + M[k][2]*V[2][1]) / fmax(s2, 1e-30);
    }
    double n1 = sqrt(u1[0]*u1[0]+u1[1]*u1[1]+u1[2]*u1[2]);
    for (int k = 0; k < 3; k++) u1[k] /= fmax(n1, 1e-30);
    double d12 = u1[0]*u2[0]+u1[1]*u2[1]+u1[2]*u2[2];
    for (int k = 0; k < 3; k++) u2[k] -= d12*u1[k];
    double n2 = sqrt(u2[0]*u2[0]+u2[1]*u2[1]+u2[2]*u2[2]);
    for (int k = 0; k < 3; k++) u2[k] /= fmax(n2, 1e-30);
    u3[0] = u1[1]*u2[2] - u1[2]*u2[1];
    u3[1] = u1[2]*u2[0] - u1[0]*u2[2];
    u3[2] = u1[0]*u2[1] - u1[1]*u2[0];

    for (int d = 0; d < 3; d++)
        for (int e = 0; e < 3; e++)
            g_R[n][3*d + e] = (float)(u1[d]*V[e][0] + u2[d]*V[e][1] + u3[d]*V[e][2]);
    for (int k = 0; k < 3; k++){ g_cp[n][k] = (float)cp[k]; g_ct[n][k] = (float)cq[k]; }
}

// ---------------- TM score ----------------
__global__ void k_tm(const float* __restrict__ pred, const float* __restrict__ mgen,
                     const float* __restrict__ tpm, float* __restrict__ avg, float inv_d02){
    int n = blockIdx.x, tid = threadIdx.x;
    float R[9];
    #pragma unroll
    for (int k = 0; k < 9; k++) R[k] = g_R[n][k];
    float cp0 = g_cp[n][0], cp1 = g_cp[n][1], cp2 = g_cp[n][2];
    float ct0 = g_ct[n][0], ct1 = g_ct[n][1], ct2 = g_ct[n][2];

    float st = 0.f, sm = 0.f;
    for (int l = tid; l < LL; l += 256){
        const float* p = pred + (size_t)(n*LL + l)*3;
        const float* q = tpm  + (size_t)(n*LL + l)*3;
        float x0 = p[0]-cp0, x1 = p[1]-cp1, x2 = p[2]-cp2;
        float a0 = x0*R[0] + x1*R[3] + x2*R[6] + ct0;
        float a1 = x0*R[1] + x1*R[4] + x2*R[7] + ct1;
        float a2 = x0*R[2] + x1*R[5] + x2*R[8] + ct2;
        float d0 = a0-q[0], d1 = a1-q[1], d2 = a2-q[2];
        float dsq = d0*d0 + d1*d1 + d2*d2;
        float tm = 1.f/(1.f + dsq*inv_d02);
        float mg = mgen[n*LL + l];
        st += tm*mg; sm += mg;
    }
    __shared__ float r1[256], r2[256];
    r1[tid] = st; r2[tid] = sm; __syncthreads();
    for (int s = 128; s; s >>= 1){
        if (tid < s){ r1[tid] += r1[tid+s]; r2[tid] += r2[tid+s]; }
        __syncthreads();
    }
    if (tid == 0) avg[n] = r1[0] / fmaxf(r2[0], 1e-6f);
}

// ---------------- launch ----------------
extern "C" void kernel_launch(void* const* d_in, const int* in_sizes, int n_in,
                              void* d_out, int out_size){
    const float* pred = (const float*)d_in[0];
    const float* tru  = (const float*)d_in[1];
    const float* mgen = (const float*)d_in[2];

    float* out   = (float*)d_out;
    float* avg   = out;                       // (N,)
    float* tpm   = out + NB;                  // (N,L,3)
    float* piout = out + NB + (size_t)NL*3;   // (N,L,L)

    k_zero<<<1, 32>>>();
    k_prep<<<NL/256, 256>>>(pred, tru, mgen);
    k_prep2<<<1, 32>>>();

    k_exp<<<1024, 256>>>();                   // build K once (only exp-heavy pass)

    for (int it = 0; it < 10; it++){
        k_mvf<<<1024, 256>>>();               // u = a / (K v)
        k_mvg<<<1024, 256>>>();               // v = b / (K^T u)
    }

    k_pi<<<1024, 512>>>(piout, tpm);
    k_kabsch<<<NB, 256>>>(pred, tpm);

    double d0 = 1.24 * cbrt((double)((LL > 16 ? LL : 16) - 15)) - 1.8;
    if (d0 < 0.5) d0 = 0.5;
    float inv_d02 = (float)(1.0/(d0*d0));
    k_tm<<<NB, 256>>>(pred, mgen, tpm, avg, inv_d02);
}